// round 2
// baseline (speedup 1.0000x reference)
#include <cuda_runtime.h>
#include <cstdint>

// WKV (RWKV v4) scan.
// One thread per (batch, channel). Blocks of 128 threads own 128 consecutive
// channels; k/v are staged through a 3-deep cp.async shared-memory pipeline
// (32 timesteps x 128 channels per tile) so the sequential T-scan never stalls
// on DRAM latency despite low occupancy (16384 threads total).
//
// Math: unnormalized linear recurrence (identical real values to the
// reference's max-stabilized form; fp32 ranges are safe for T<=1024, N(0,1)
// inputs):
//   A_t = lam*A_{t-1} + e^{k_t} v_t ,  B_t = lam*B_{t-1} + e^{k_t}
//   y_t = (A_{t-1} + e^u e^{k_t} v_t) / (B_{t-1} + e^u e^{k_t})
// with lam = exp(-exp(time_decay[c])), e^u = exp(time_first[c]) precomputed.

constexpr int CH   = 128;  // channels per block == threads per block
constexpr int TT   = 32;   // timesteps per tile
constexpr int NBUF = 3;    // pipeline depth
constexpr int SMEM_BYTES = NBUF * 2 * TT * CH * (int)sizeof(float); // 96 KB

__device__ __forceinline__ void cpasync16(float* s, const float* g) {
    unsigned sa = (unsigned)__cvta_generic_to_shared(s);
    asm volatile("cp.async.cg.shared.global [%0], [%1], 16;\n"
                 :: "r"(sa), "l"(g) : "memory");
}

// Robustly decode a device scalar that may be stored as int32 or float32.
__device__ __forceinline__ int read_dim(const void* p) {
    int i = *reinterpret_cast<const int*>(p);
    if (i >= 1 && i <= (1 << 20)) return i;
    float f = *reinterpret_cast<const float*>(p);
    int fi = (int)f;
    return (fi >= 1) ? fi : 1;
}

__global__ __launch_bounds__(CH, 1)
void wkv_kernel(const void* __restrict__ seqlen_p,
                const float* __restrict__ td,
                const float* __restrict__ tf,
                const float* __restrict__ kg,
                const float* __restrict__ vg,
                float* __restrict__ out,
                int C, long long BTC)
{
    extern __shared__ float smem[]; // [NBUF][2][TT][CH]
    const int tid = threadIdx.x;

    const int T = read_dim(seqlen_p);
    const long long BT = BTC / C;
    const int B = (int)(BT / T);
    const int ctiles = (C + CH - 1) / CH;
    const int nwork = B * ctiles;
    const int ntiles = (T + TT - 1) / TT;
    const bool vec_ok = ((C & 3) == 0) &&
                        ((((uintptr_t)kg) & 15) == 0) &&
                        ((((uintptr_t)vg) & 15) == 0);

    for (int w = blockIdx.x; w < nwork; w += gridDim.x) {
        const int b  = w / ctiles;
        const int c0 = (w % ctiles) * CH;
        const int c  = c0 + tid;
        const bool valid = (c < C);

        float lam = 0.f, eu = 0.f;
        if (valid) {
            lam = __expf(-__expf(td[c]));
            eu  = __expf(tf[c]);
        }
        float A = 0.f, Bs = 0.f;

        const float* kbase = kg + (long long)b * T * C;
        const float* vbase = vg + (long long)b * T * C;
        const long long obase = (long long)b * T * C + c;

        auto load_tile = [&](int tile) {
            const int buf = tile % NBUF;
            float* sk = smem + (size_t)buf * 2 * TT * CH;
            float* sv = sk + TT * CH;
            const int t0 = tile * TT;
            if (vec_ok) {
                // TT*CH/4 = 1024 16B chunks, 8 per thread. 32 chunks per row.
                #pragma unroll
                for (int j = 0; j < TT / 4; ++j) {
                    const int q    = tid + j * CH;
                    const int row  = q >> 5;
                    const int col4 = (q & 31) * 4;
                    int gt = t0 + row; if (gt >= T) gt = T - 1;
                    const int gc = c0 + col4;
                    if (gc + 4 <= C) {
                        const long long go = (long long)gt * C + gc;
                        cpasync16(sk + row * CH + col4, kbase + go);
                        cpasync16(sv + row * CH + col4, vbase + go);
                    }
                }
            } else {
                for (int r = 0; r < TT; ++r) {
                    int gt = t0 + r; if (gt >= T) gt = T - 1;
                    const int gc = c0 + tid;
                    if (gc < C) {
                        const long long go = (long long)gt * C + gc;
                        sk[r * CH + tid] = kbase[go];
                        sv[r * CH + tid] = vbase[go];
                    }
                }
            }
        };

        // Preload pipeline (always commit to keep group counts aligned).
        #pragma unroll
        for (int p = 0; p < NBUF - 1; ++p) {
            if (p < ntiles) load_tile(p);
            asm volatile("cp.async.commit_group;\n" ::);
        }

        for (int tile = 0; tile < ntiles; ++tile) {
            asm volatile("cp.async.wait_group %0;\n" :: "n"(NBUF - 2));
            __syncthreads();

            const int buf = tile % NBUF;
            const float* sk = smem + (size_t)buf * 2 * TT * CH + tid;
            const float* sv = sk + TT * CH;
            const int t0 = tile * TT;
            int jmax = T - t0; if (jmax > TT) jmax = TT;

            #pragma unroll
            for (int j = 0; j < TT; ++j) {
                if (j < jmax) {
                    const float kt  = sk[j * CH];
                    const float vt  = sv[j * CH];
                    const float ek  = __expf(kt);
                    const float eku = eu * ek;
                    const float num = fmaf(eku, vt, A);
                    const float den = Bs + eku;
                    if (valid)
                        out[obase + (long long)(t0 + j) * C] = __fdividef(num, den);
                    A  = fmaf(lam, A,  ek * vt);
                    Bs = fmaf(lam, Bs, ek);
                }
            }
            __syncthreads();

            const int nt = tile + NBUF - 1;
            if (nt < ntiles) load_tile(nt);
            asm volatile("cp.async.commit_group;\n" ::);
        }
        asm volatile("cp.async.wait_group 0;\n" ::);
        __syncthreads();
    }
}

extern "C" void kernel_launch(void* const* d_in, const int* in_sizes, int n_in,
                              void* d_out, int out_size)
{
    // metadata order: batch_size, seq_len, embedding_dim, time_decay,
    //                 time_first, k, v
    const void*  seqlen_p = d_in[1];
    const float* td = (const float*)d_in[3];
    const float* tf = (const float*)d_in[4];
    const float* k  = (const float*)d_in[5];
    const float* v  = (const float*)d_in[6];
    float* out = (float*)d_out;

    const int C = in_sizes[3];
    const long long BTC = in_sizes[5];

    cudaFuncSetAttribute(wkv_kernel,
                         cudaFuncAttributeMaxDynamicSharedMemorySize,
                         SMEM_BYTES);

    // Persistent grid: T (and thus B, nwork) is only known on-device, so
    // launch a fixed grid and let blocks self-schedule / early-exit.
    wkv_kernel<<<1024, CH, SMEM_BYTES>>>(seqlen_p, td, tf, k, v, out, C, BTC);
}

// round 3
// speedup vs baseline: 1.5788x; 1.5788x over previous
#include <cuda_runtime.h>
#include <cstdint>

// WKV (RWKV v4) scan — 3-pass segmented linear scan.
//
// state_t = lam*state_{t-1} + e^{k_t} * (v_t, 1),  lam = exp(-exp(td[c]))
// y_t = (A_{t-1} + e^u e^{k_t} v_t) / (B_{t-1} + e^u e^{k_t})
//
// Pass 1: per (b, channel-tile, segment) block: local scan from zero init,
//         store segment-final (A,B) to scratch.   [reads k,v once]
// Pass 2: per (b,c) thread: chain the S segment states with decay lam^L,
//         rewriting scratch in place as EXCLUSIVE prefixes (= seeds).
// Pass 3: same block layout as pass 1, seeded from scratch, emit y.
//         [reads k,v again, writes y]
//
// Parallelism: nwork = B * (C/128) * S = 1024 blocks (vs 128 single-pass),
// 48KB smem/block -> 4 blocks/SM -> 4 warps/SMSP to hide MUFU/LDS/FMA latency.

constexpr int CH   = 128;  // channels per block == threads per block
constexpr int TT   = 16;   // timesteps per smem tile
constexpr int NBUF = 3;    // cp.async pipeline depth
constexpr int S    = 8;    // T segments
constexpr int SMEM_BYTES = NBUF * 2 * TT * CH * (int)sizeof(float); // 48 KB
constexpr int GRID_SCAN  = 1024;

__device__ float g_Aloc[1 << 20];
__device__ float g_Bloc[1 << 20];

__device__ __forceinline__ void cpasync16(float* s, const float* g) {
    unsigned sa = (unsigned)__cvta_generic_to_shared(s);
    asm volatile("cp.async.cg.shared.global [%0], [%1], 16;\n"
                 :: "r"(sa), "l"(g) : "memory");
}

// Robustly decode a device scalar that may be stored as int32 or float32.
__device__ __forceinline__ int read_dim(const void* p) {
    int i = *reinterpret_cast<const int*>(p);
    if (i >= 1 && i <= (1 << 20)) return i;
    float f = *reinterpret_cast<const float*>(p);
    int fi = (int)f;
    return (fi >= 1) ? fi : 1;
}

template <bool WRITE_OUT>
__global__ __launch_bounds__(CH, 4)
void wkv_scan_kernel(const void* __restrict__ seqlen_p,
                     const float* __restrict__ td,
                     const float* __restrict__ tf,
                     const float* __restrict__ kg,
                     const float* __restrict__ vg,
                     float* __restrict__ out,
                     int C, long long BTC)
{
    extern __shared__ float smem[]; // [NBUF][2][TT][CH]
    const int tid = threadIdx.x;

    const int T = read_dim(seqlen_p);
    const long long BT = BTC / C;
    const int B = (int)(BT / T);
    const int ctiles = (C + CH - 1) / CH;
    const int seglen = (T + S - 1) / S;
    const int nwork = B * ctiles * S;
    const long long BC = (long long)B * C;
    const bool vec_ok = ((C & 3) == 0) &&
                        ((((uintptr_t)kg) & 15) == 0) &&
                        ((((uintptr_t)vg) & 15) == 0);

    for (int w = blockIdx.x; w < nwork; w += gridDim.x) {
        const int s     = w % S;
        const int rowid = w / S;
        const int b     = rowid / ctiles;
        const int c0    = (rowid % ctiles) * CH;
        const int c     = c0 + tid;
        const bool valid = (c < C);

        const int segstart = s * seglen;
        const int segend   = min(T, segstart + seglen);
        const long long sidx = (long long)s * BC + (long long)b * C + c;

        if (segstart >= segend) {  // empty segment: identity contribution
            if (!WRITE_OUT && valid) { g_Aloc[sidx] = 0.f; g_Bloc[sidx] = 0.f; }
            continue;
        }

        float lam = 0.f, eu = 0.f, A = 0.f, Bs = 0.f;
        if (valid) {
            lam = __expf(-__expf(td[c]));
            if (WRITE_OUT) {
                eu = __expf(tf[c]);
                A  = g_Aloc[sidx];   // exclusive prefix = seed state
                Bs = g_Bloc[sidx];
            }
        }

        const float* kbase = kg + (long long)b * T * C;
        const float* vbase = vg + (long long)b * T * C;
        const long long obase = (long long)b * T * C + c;
        const int ntiles = (segend - segstart + TT - 1) / TT;

        auto load_tile = [&](int tile) {
            const int buf = tile % NBUF;
            float* sk = smem + (size_t)buf * 2 * TT * CH;
            float* sv = sk + TT * CH;
            const int t0 = segstart + tile * TT;
            if (vec_ok) {
                #pragma unroll
                for (int j = 0; j < TT / 4; ++j) {
                    const int q    = tid + j * CH;
                    const int row  = q >> 5;
                    const int col4 = (q & 31) * 4;
                    int gt = t0 + row; if (gt >= segend) gt = segend - 1;
                    const int gc = c0 + col4;
                    if (gc + 4 <= C) {
                        const long long go = (long long)gt * C + gc;
                        cpasync16(sk + row * CH + col4, kbase + go);
                        cpasync16(sv + row * CH + col4, vbase + go);
                    }
                }
            } else {
                for (int r = 0; r < TT; ++r) {
                    int gt = t0 + r; if (gt >= segend) gt = segend - 1;
                    if (valid) {
                        const long long go = (long long)gt * C + c;
                        sk[r * CH + tid] = kbase[go];
                        sv[r * CH + tid] = vbase[go];
                    }
                }
            }
        };

        #pragma unroll
        for (int p = 0; p < NBUF - 1; ++p) {
            if (p < ntiles) load_tile(p);
            asm volatile("cp.async.commit_group;\n" ::);
        }

        for (int tile = 0; tile < ntiles; ++tile) {
            asm volatile("cp.async.wait_group %0;\n" :: "n"(NBUF - 2));
            __syncthreads();

            const int buf = tile % NBUF;
            const float* sk = smem + (size_t)buf * 2 * TT * CH + tid;
            const float* sv = sk + TT * CH;
            const int t0 = segstart + tile * TT;
            const int jmax = min(TT, segend - t0);

            if (jmax == TT) {
                #pragma unroll
                for (int j = 0; j < TT; ++j) {
                    const float kt = sk[j * CH];
                    const float vt = sv[j * CH];
                    const float ek = __expf(kt);
                    if (WRITE_OUT) {
                        const float eku = eu * ek;
                        const float y = __fdividef(fmaf(eku, vt, A), Bs + eku);
                        if (valid)
                            out[obase + (long long)(t0 + j) * C] = y;
                    }
                    A  = fmaf(lam, A,  ek * vt);
                    Bs = fmaf(lam, Bs, ek);
                }
            } else {
                for (int j = 0; j < jmax; ++j) {
                    const float kt = sk[j * CH];
                    const float vt = sv[j * CH];
                    const float ek = __expf(kt);
                    if (WRITE_OUT) {
                        const float eku = eu * ek;
                        const float y = __fdividef(fmaf(eku, vt, A), Bs + eku);
                        if (valid)
                            out[obase + (long long)(t0 + j) * C] = y;
                    }
                    A  = fmaf(lam, A,  ek * vt);
                    Bs = fmaf(lam, Bs, ek);
                }
            }
            __syncthreads();

            const int nt = tile + NBUF - 1;
            if (nt < ntiles) load_tile(nt);
            asm volatile("cp.async.commit_group;\n" ::);
        }
        asm volatile("cp.async.wait_group 0;\n" ::);
        __syncthreads();

        if (!WRITE_OUT && valid) { g_Aloc[sidx] = A; g_Bloc[sidx] = Bs; }
    }
}

// Pass 2: chain segment states per (b,c); rewrite scratch as exclusive prefixes.
__global__ __launch_bounds__(256)
void wkv_chain_kernel(const void* __restrict__ seqlen_p,
                      const float* __restrict__ td,
                      int C, long long BTC)
{
    const int T = read_dim(seqlen_p);
    const long long BT = BTC / C;
    const int B = (int)(BT / T);
    const int seglen = (T + S - 1) / S;
    const long long BC = (long long)B * C;

    for (long long i = blockIdx.x * blockDim.x + threadIdx.x; i < BC;
         i += (long long)gridDim.x * blockDim.x) {
        const int c = (int)(i % C);
        const float ew = __expf(td[c]);
        float A = 0.f, Bs = 0.f;
        #pragma unroll
        for (int s = 0; s < S; ++s) {
            const long long idx = (long long)s * BC + i;
            const float ta = g_Aloc[idx];
            const float tb = g_Bloc[idx];
            g_Aloc[idx] = A;
            g_Bloc[idx] = Bs;
            int Ls = T - s * seglen;
            Ls = max(0, min(seglen, Ls));
            const float f = __expf(-(float)Ls * ew);  // lam^Ls
            A  = fmaf(f, A,  ta);
            Bs = fmaf(f, Bs, tb);
        }
    }
}

extern "C" void kernel_launch(void* const* d_in, const int* in_sizes, int n_in,
                              void* d_out, int out_size)
{
    // metadata order: batch_size, seq_len, embedding_dim, time_decay,
    //                 time_first, k, v
    const void*  seqlen_p = d_in[1];
    const float* td = (const float*)d_in[3];
    const float* tf = (const float*)d_in[4];
    const float* k  = (const float*)d_in[5];
    const float* v  = (const float*)d_in[6];
    float* out = (float*)d_out;

    const int C = in_sizes[3];
    const long long BTC = in_sizes[5];

    static bool attr_done = false;
    if (!attr_done) {
        cudaFuncSetAttribute(wkv_scan_kernel<false>,
                             cudaFuncAttributeMaxDynamicSharedMemorySize,
                             SMEM_BYTES);
        cudaFuncSetAttribute(wkv_scan_kernel<true>,
                             cudaFuncAttributeMaxDynamicSharedMemorySize,
                             SMEM_BYTES);
        attr_done = true;
    }

    wkv_scan_kernel<false><<<GRID_SCAN, CH, SMEM_BYTES>>>(
        seqlen_p, td, tf, k, v, out, C, BTC);
    wkv_chain_kernel<<<64, 256>>>(seqlen_p, td, C, BTC);
    wkv_scan_kernel<true><<<GRID_SCAN, CH, SMEM_BYTES>>>(
        seqlen_p, td, tf, k, v, out, C, BTC);
}

// round 4
// speedup vs baseline: 1.7221x; 1.0908x over previous
#include <cuda_runtime.h>
#include <cstdint>

// WKV (RWKV v4) — single-kernel segmented scan with decoupled lookback.
//
//   state_t = lam*state_{t-1} + e^{k_t}(v_t, 1),  lam = exp(-exp(td[c]))
//   y_t = (A_{t-1} + e^u e^{k_t} v_t) / (B_{t-1} + e^u e^{k_t})
//
// Work item w = (row, segment): row = (batch, 128-channel tile).
//   sweep 1: local scan of the segment from zero init            (reads k,v)
//   publish: store local (A,B) to scratch, release flag
//   lookback: fold predecessor locals j<s: seed = lam^{L_j} seed + local_j
//   sweep 2: re-scan seeded, emit y   (segment is L2-hot from sweep 1)
// DRAM traffic ~= k+v read once + y write (sweep-2 re-read hits L2).
// Lookback waits only on strictly-lower blockIdx, after publishing own
// local -> deadlock-free regardless of residency (CUB-style ordering).

constexpr int CH    = 128;  // channels per block == threads
constexpr int TT    = 8;    // timesteps per smem tile
constexpr int NBUF  = 3;    // cp.async pipeline depth
constexpr int S_MAX = 8;    // max T segments
constexpr int GRID  = 1024;
constexpr int SMEM_BYTES = NBUF * 2 * TT * CH * (int)sizeof(float); // 24 KB

__device__ float    g_A[1 << 18];
__device__ float    g_B[1 << 18];
__device__ unsigned g_flag[GRID];

__device__ __forceinline__ void cpasync16(float* s, const float* g) {
    unsigned sa = (unsigned)__cvta_generic_to_shared(s);
    asm volatile("cp.async.cg.shared.global [%0], [%1], 16;\n"
                 :: "r"(sa), "l"(g) : "memory");
}

__device__ __forceinline__ int read_dim(const void* p) {
    int i = *reinterpret_cast<const int*>(p);
    if (i >= 1 && i <= (1 << 20)) return i;
    float f = *reinterpret_cast<const float*>(p);
    int fi = (int)f;
    return (fi >= 1) ? fi : 1;
}

__global__ void wkv_zero_flags() {
    int i = blockIdx.x * blockDim.x + threadIdx.x;
    if (i < GRID) g_flag[i] = 0u;
}

template <bool EMIT>
__device__ __forceinline__ void scan_segment(
    float* smem, int tid,
    const float* __restrict__ kbase, const float* __restrict__ vbase,
    float* __restrict__ obase,            // out + b*T*C + c (EMIT only)
    int segstart, int segend, int C, int c0,
    bool valid, bool vec_ok, float lam, float eu,
    float& A, float& Bs)
{
    const int ntiles = (segend - segstart + TT - 1) / TT;

    auto load_tile = [&](int tile) {
        const int buf = tile % NBUF;
        float* sk = smem + (size_t)buf * 2 * TT * CH;
        float* sv = sk + TT * CH;
        const int t0 = segstart + tile * TT;
        if (vec_ok) {
            #pragma unroll
            for (int j = 0; j < TT / 4; ++j) {
                const int q    = tid + j * CH;
                const int row  = q >> 5;
                const int col4 = (q & 31) * 4;
                int gt = t0 + row; if (gt >= segend) gt = segend - 1;
                const int gc = c0 + col4;
                if (gc + 4 <= C) {
                    const long long go = (long long)gt * C + gc;
                    cpasync16(sk + row * CH + col4, kbase + go);
                    cpasync16(sv + row * CH + col4, vbase + go);
                }
            }
        } else {
            for (int r = 0; r < TT; ++r) {
                int gt = t0 + r; if (gt >= segend) gt = segend - 1;
                if (valid) {
                    const long long go = (long long)gt * C + (c0 + tid);
                    sk[r * CH + tid] = kbase[go];
                    sv[r * CH + tid] = vbase[go];
                }
            }
        }
    };

    #pragma unroll
    for (int p = 0; p < NBUF - 1; ++p) {
        if (p < ntiles) load_tile(p);
        asm volatile("cp.async.commit_group;\n" ::);
    }

    for (int tile = 0; tile < ntiles; ++tile) {
        asm volatile("cp.async.wait_group %0;\n" :: "n"(NBUF - 2));
        __syncthreads();

        const int buf = tile % NBUF;
        const float* sk = smem + (size_t)buf * 2 * TT * CH + tid;
        const float* sv = sk + TT * CH;
        const int t0 = segstart + tile * TT;
        const int jmax = min(TT, segend - t0);

        #pragma unroll
        for (int j = 0; j < TT; ++j) {
            if (j < jmax) {
                const float kt = sk[j * CH];
                const float vt = sv[j * CH];
                const float ek = __expf(kt);
                if (EMIT) {
                    const float eku = eu * ek;
                    const float y = __fdividef(fmaf(eku, vt, A), Bs + eku);
                    if (valid)
                        obase[(long long)(t0 + j) * C] = y;
                }
                A  = fmaf(lam, A,  ek * vt);
                Bs = fmaf(lam, Bs, ek);
            }
        }
        __syncthreads();

        const int nt = tile + NBUF - 1;
        if (nt < ntiles) load_tile(nt);
        asm volatile("cp.async.commit_group;\n" ::);
    }
    asm volatile("cp.async.wait_group 0;\n" ::);
    __syncthreads();
}

__global__ __launch_bounds__(CH, 8)
void wkv_lookback_kernel(const void* __restrict__ seqlen_p,
                         const float* __restrict__ td,
                         const float* __restrict__ tf,
                         const float* __restrict__ kg,
                         const float* __restrict__ vg,
                         float* __restrict__ out,
                         int C, long long BTC)
{
    extern __shared__ float smem[];
    const int tid = threadIdx.x;

    const int T = read_dim(seqlen_p);
    const long long BT = BTC / C;
    const int B = (int)(BT / T);
    const int ctiles = (C + CH - 1) / CH;
    const int nrows  = B * ctiles;
    int S_eff = (int)(gridDim.x / nrows);
    if (S_eff < 1) S_eff = 1;
    if (S_eff > S_MAX) S_eff = S_MAX;
    const int seglen = (T + S_eff - 1) / S_eff;
    const int nwork  = nrows * S_eff;
    const bool vec_ok = ((C & 3) == 0) &&
                        ((((uintptr_t)kg) & 15) == 0) &&
                        ((((uintptr_t)vg) & 15) == 0);

    for (int w = blockIdx.x; w < nwork; w += gridDim.x) {
        const int s     = w % S_eff;
        const int rowid = w / S_eff;
        const int b     = rowid / ctiles;
        const int c0    = (rowid % ctiles) * CH;
        const int c     = c0 + tid;
        const bool valid = (c < C);

        const int segstart = min(s * seglen, T);
        const int segend   = min(T, segstart + seglen);

        const float ew  = valid ? __expf(td[c]) : 0.f;  // e^{td}
        const float lam = __expf(-ew);                  // exp(-e^{td})

        const float* kbase = kg + (long long)b * T * C;
        const float* vbase = vg + (long long)b * T * C;
        float* obase = out + (long long)b * T * C + c;

        // ---- sweep 1: local scan from zero init ----
        float A = 0.f, Bs = 0.f;
        if (segstart < segend)
            scan_segment<false>(smem, tid, kbase, vbase, nullptr,
                                segstart, segend, C, c0, valid, vec_ok,
                                lam, 0.f, A, Bs);

        // ---- publish local state, release flag ----
        if (S_eff > 1) {
            const size_t st = (size_t)w * CH + tid;
            g_A[st] = A;
            g_B[st] = Bs;
            __threadfence();
            __syncthreads();
            if (tid == 0) atomicExch(&g_flag[w], 1u);
        }

        // ---- lookback: fold predecessor locals into seed ----
        float sa = 0.f, sb = 0.f;
        for (int j = 0; j < s; ++j) {
            const int wj = rowid * S_eff + j;
            if (tid == 0) {
                volatile unsigned* f = &g_flag[wj];
                while (*f == 0u) __nanosleep(64);
            }
            __syncthreads();
            int Lj = T - j * seglen;
            Lj = max(0, min(seglen, Lj));
            const float fdec = __expf(-(float)Lj * ew);  // lam^{L_j}
            const size_t st = (size_t)wj * CH + tid;
            sa = fmaf(fdec, sa, __ldcg(&g_A[st]));
            sb = fmaf(fdec, sb, __ldcg(&g_B[st]));
        }

        // ---- sweep 2: seeded re-scan, emit y (segment L2-hot) ----
        if (segstart < segend) {
            const float eu = valid ? __expf(tf[c]) : 0.f;
            A = sa; Bs = sb;
            scan_segment<true>(smem, tid, kbase, vbase, obase,
                               segstart, segend, C, c0, valid, vec_ok,
                               lam, eu, A, Bs);
        }
    }
}

extern "C" void kernel_launch(void* const* d_in, const int* in_sizes, int n_in,
                              void* d_out, int out_size)
{
    // metadata order: batch_size, seq_len, embedding_dim, time_decay,
    //                 time_first, k, v
    const void*  seqlen_p = d_in[1];
    const float* td = (const float*)d_in[3];
    const float* tf = (const float*)d_in[4];
    const float* k  = (const float*)d_in[5];
    const float* v  = (const float*)d_in[6];
    float* out = (float*)d_out;

    const int C = in_sizes[3];
    const long long BTC = in_sizes[5];

    static bool attr_done = false;
    if (!attr_done) {
        cudaFuncSetAttribute(wkv_lookback_kernel,
                             cudaFuncAttributeMaxDynamicSharedMemorySize,
                             SMEM_BYTES);
        attr_done = true;
    }

    wkv_zero_flags<<<(GRID + 255) / 256, 256>>>();
    wkv_lookback_kernel<<<GRID, CH, SMEM_BYTES>>>(
        seqlen_p, td, tf, k, v, out, C, BTC);
}